// round 13
// baseline (speedup 1.0000x reference)
#include <cuda_runtime.h>
#include <cuda_fp16.h>
#include <cuda_bf16.h>
#include <cstdint>

// Problem constants: N_NODES=50000, N_EDGES=640000, D=128, OUT=1
#define MAX_NODES 50000
#define D 128
#define CHUNK_N 12500                       // nodes per pipeline chunk (x4)
#define CHUNK_BYTES (CHUNK_N * 4)           // 50000 B (16B multiple)
#define TABLE_BYTES (MAX_NODES * 4)         // 200000 B of __half2
#define SMEM_TOTAL (TABLE_BYTES + 16 + 2 * D * 4)

// Packed per-node projections: lo = dot(X[n],W1), hi = dot(X[n],W2), fp16.
__device__ __align__(16) __half2 d_pack[MAX_NODES];
// Per-chunk monotonic arrival counters (generation trick => replay-safe).
__device__ unsigned long long d_ctr[4];

__device__ __forceinline__ float dot4(float4 a, float4 b) {
    return a.x * b.x + a.y * b.y + a.z * b.z + a.w * b.w;
}

#define CLAMP(v) min(max((v), 0), MAX_NODES - 1)

// Pipelined fused kernel, one block per SM.
//   warps 0-30: compute node projections chunk-by-chunk, bar.arrive per chunk
//   warp 31 lane 0: per chunk: bar.sync -> signal counter -> poll all blocks
//                   done -> cp.async.bulk that chunk into smem (overlaps
//                   later chunks' compute)
//   everyone: prefetch ei to L2 at start; after phase A, load indices,
//             mbarrier-wait for the full table, gather from smem, store.
__global__ void __launch_bounds__(1024, 1)
fused_kernel(const float* __restrict__ X,
             const int* __restrict__ ei,
             const float* __restrict__ W1,
             const float* __restrict__ W2,
             float* __restrict__ out,
             int n_nodes, int n_edges) {
    extern __shared__ __align__(16) unsigned char smem_raw[];
    __half2* s_p = reinterpret_cast<__half2*>(smem_raw);
    float* sW1 = reinterpret_cast<float*>(smem_raw + TABLE_BYTES + 16);
    float* sW2 = sW1 + D;

    uint32_t smem_base;
    asm("{ .reg .u64 t; cvta.to.shared.u64 t, %1; cvt.u32.u64 %0, t; }"
        : "=r"(smem_base) : "l"(smem_raw));
    uint32_t mbar = smem_base + TABLE_BYTES;

    int tid = threadIdx.x;
    int G = gridDim.x;
    int bx = blockIdx.x;
    int wid = tid >> 5;
    int lane = tid & 31;
    int sub = lane & 7;
    int grp = lane >> 3;

    if (tid == 992) {
        asm volatile("mbarrier.init.shared.b64 [%0], 1;" :: "r"(mbar) : "memory");
    }
    if (tid < D) {
        sW1[tid] = W1[tid];
        sW2[tid] = W2[tid];
    }

    // Edge ranges + L2 prefetch of index lines (hidden under phase A).
    int total_quads = n_edges >> 2;
    int qpb = (total_quads + G - 1) / G;
    int q_start = bx * qpb;
    int q_end = min(q_start + qpb, total_quads);
    int q0 = q_start + tid;
    int q1 = q0 + 1024;
    bool v0 = q0 < q_end;
    bool v1 = q1 < q_end;
    if (v0) {
        asm volatile("prefetch.global.L2 [%0];" :: "l"(ei + q0 * 4));
        asm volatile("prefetch.global.L2 [%0];" :: "l"(ei + n_edges + q0 * 4));
    }
    if (v1) {
        asm volatile("prefetch.global.L2 [%0];" :: "l"(ei + q1 * 4));
        asm volatile("prefetch.global.L2 [%0];" :: "l"(ei + n_edges + q1 * 4));
    }
    __syncthreads();   // mbar init + sW visible to all

    int npb = (CHUNK_N + G - 1) / G;   // nodes per block per chunk (83 @ G=152)

    if (wid < 31) {
        // ---- Compute warps: phase A, chunked ----
        const float4* Xv = reinterpret_cast<const float4*>(X);
        const float4* w1 = reinterpret_cast<const float4*>(sW1);
        const float4* w2 = reinterpret_cast<const float4*>(sW2);
        float4 w1_0 = w1[sub], w1_1 = w1[sub + 8], w1_2 = w1[sub + 16], w1_3 = w1[sub + 24];
        float4 w2_0 = w2[sub], w2_1 = w2[sub + 8], w2_2 = w2[sub + 16], w2_3 = w2[sub + 24];

        #pragma unroll
        for (int c = 0; c < 4; c++) {
            int cbase = c * CHUNK_N;
            int nstart = cbase + bx * npb;
            int nend = min(nstart + npb, cbase + CHUNK_N);
            int rowA = nstart + wid * 8 + grp;
            int rowB = rowA + 4;

            float sA1 = 0.f, sA2 = 0.f, sB1 = 0.f, sB2 = 0.f;
            if (rowA < nend) {
                float4 a0 = Xv[(size_t)rowA * 32 + sub + 0];
                float4 a1 = Xv[(size_t)rowA * 32 + sub + 8];
                float4 a2 = Xv[(size_t)rowA * 32 + sub + 16];
                float4 a3 = Xv[(size_t)rowA * 32 + sub + 24];
                sA1 = dot4(a0, w1_0) + dot4(a1, w1_1) + dot4(a2, w1_2) + dot4(a3, w1_3);
                sA2 = dot4(a0, w2_0) + dot4(a1, w2_1) + dot4(a2, w2_2) + dot4(a3, w2_3);
            }
            if (rowB < nend) {
                float4 b0 = Xv[(size_t)rowB * 32 + sub + 0];
                float4 b1 = Xv[(size_t)rowB * 32 + sub + 8];
                float4 b2 = Xv[(size_t)rowB * 32 + sub + 16];
                float4 b3 = Xv[(size_t)rowB * 32 + sub + 24];
                sB1 = dot4(b0, w1_0) + dot4(b1, w1_1) + dot4(b2, w1_2) + dot4(b3, w1_3);
                sB2 = dot4(b0, w2_0) + dot4(b1, w2_1) + dot4(b2, w2_2) + dot4(b3, w2_3);
            }

            #pragma unroll
            for (int off = 4; off > 0; off >>= 1) {
                sA1 += __shfl_xor_sync(0xFFFFFFFF, sA1, off);
                sA2 += __shfl_xor_sync(0xFFFFFFFF, sA2, off);
                sB1 += __shfl_xor_sync(0xFFFFFFFF, sB1, off);
                sB2 += __shfl_xor_sync(0xFFFFFFFF, sB2, off);
            }

            if (sub == 0) {
                if (rowA < nend) d_pack[rowA] = __floats2half2_rn(sA1, sA2);
                if (rowB < nend) d_pack[rowB] = __floats2half2_rn(sB1, sB2);
            }

            // Producer arrive: compute warps do NOT block.
            asm volatile("bar.arrive %0, 1024;" :: "r"(c + 1) : "memory");
        }
    } else {
        // ---- Orchestrator warp (31): per-chunk sync -> signal -> poll -> fill ----
        #pragma unroll
        for (int c = 0; c < 4; c++) {
            asm volatile("bar.sync %0, 1024;" :: "r"(c + 1) : "memory");
            if (lane == 0) {
                __threadfence();
                unsigned long long old = atomicAdd(&d_ctr[c], 1ULL);
                unsigned long long tgt = (old / G + 1) * (unsigned long long)G;
                unsigned long long cur;
                do {
                    asm volatile("ld.acquire.gpu.u64 %0, [%1];"
                                 : "=l"(cur) : "l"(&d_ctr[c]) : "memory");
                } while (cur < tgt);
                asm volatile("fence.proxy.async;" ::: "memory");
                if (c == 0) {
                    asm volatile("mbarrier.arrive.expect_tx.shared.b64 _, [%0], %1;"
                                 :: "r"(mbar), "r"((uint32_t)TABLE_BYTES) : "memory");
                }
                const char* src = reinterpret_cast<const char*>(d_pack) + (size_t)c * CHUNK_BYTES;
                asm volatile(
                    "cp.async.bulk.shared::cta.global.mbarrier::complete_tx::bytes "
                    "[%0], [%1], %2, [%3];"
                    :: "r"(smem_base + c * CHUNK_BYTES), "l"(src),
                       "r"((uint32_t)CHUNK_BYTES), "r"(mbar) : "memory");
            }
        }
    }

    // ---- All threads: load indices (L2-hot from prefetch) ----
    int4 s4a = make_int4(0,0,0,0), d4a = s4a, s4b = s4a, d4b = s4a;
    if (v0) {
        s4a = *reinterpret_cast<const int4*>(ei + q0 * 4);
        d4a = *reinterpret_cast<const int4*>(ei + n_edges + q0 * 4);
    }
    if (v1) {
        s4b = *reinterpret_cast<const int4*>(ei + q1 * 4);
        d4b = *reinterpret_cast<const int4*>(ei + n_edges + q1 * 4);
    }

    // ---- Wait for the full table (4 x 50000 B complete_tx) ----
    {
        uint32_t done;
        asm volatile(
            "{\n\t"
            ".reg .pred p;\n\t"
            "mbarrier.try_wait.parity.acquire.cta.shared::cta.b64 p, [%1], 0;\n\t"
            "selp.b32 %0, 1, 0, p;\n\t"
            "}"
            : "=r"(done) : "r"(mbar) : "memory");
        if (!done) {
            asm volatile(
                "{\n\t"
                ".reg .pred P1;\n\t"
                "WL_%=:\n\t"
                "mbarrier.try_wait.parity.acquire.cta.shared::cta.b64 P1, [%0], 0, 0x989680;\n\t"
                "@P1 bra.uni WD_%=;\n\t"
                "bra.uni WL_%=;\n\t"
                "WD_%=:\n\t"
                "}"
                :: "r"(mbar) : "memory");
        }
    }

    // ---- Gather + store ----
    if (v0) {
        float4 r;
        r.x = __low2float(s_p[CLAMP(s4a.x)]) + __high2float(s_p[CLAMP(d4a.x)]);
        r.y = __low2float(s_p[CLAMP(s4a.y)]) + __high2float(s_p[CLAMP(d4a.y)]);
        r.z = __low2float(s_p[CLAMP(s4a.z)]) + __high2float(s_p[CLAMP(d4a.z)]);
        r.w = __low2float(s_p[CLAMP(s4a.w)]) + __high2float(s_p[CLAMP(d4a.w)]);
        *reinterpret_cast<float4*>(out + q0 * 4) = r;
    }
    if (v1) {
        float4 r;
        r.x = __low2float(s_p[CLAMP(s4b.x)]) + __high2float(s_p[CLAMP(d4b.x)]);
        r.y = __low2float(s_p[CLAMP(s4b.y)]) + __high2float(s_p[CLAMP(d4b.y)]);
        r.z = __low2float(s_p[CLAMP(s4b.z)]) + __high2float(s_p[CLAMP(d4b.z)]);
        r.w = __low2float(s_p[CLAMP(s4b.w)]) + __high2float(s_p[CLAMP(d4b.w)]);
        *reinterpret_cast<float4*>(out + q1 * 4) = r;
    }
    // Generic leftover (qpb > 2048) — not hit at current sizes.
    for (int q = q_start + 2 * 1024 + tid; q < q_end; q += 1024) {
        int4 s4 = *reinterpret_cast<const int4*>(ei + q * 4);
        int4 d4 = *reinterpret_cast<const int4*>(ei + n_edges + q * 4);
        float4 r;
        r.x = __low2float(s_p[CLAMP(s4.x)]) + __high2float(s_p[CLAMP(d4.x)]);
        r.y = __low2float(s_p[CLAMP(s4.y)]) + __high2float(s_p[CLAMP(d4.y)]);
        r.z = __low2float(s_p[CLAMP(s4.z)]) + __high2float(s_p[CLAMP(d4.z)]);
        r.w = __low2float(s_p[CLAMP(s4.w)]) + __high2float(s_p[CLAMP(d4.w)]);
        *reinterpret_cast<float4*>(out + q * 4) = r;
    }
    // Scalar tail (n_edges % 4 != 0) — block 0 only.
    if (bx == 0) {
        for (int e = total_quads * 4 + tid; e < n_edges; e += blockDim.x) {
            int s = CLAMP(ei[e]);
            int d = CLAMP(ei[n_edges + e]);
            out[e] = __low2float(s_p[s]) + __high2float(s_p[d]);
        }
    }
}

extern "C" void kernel_launch(void* const* d_in, const int* in_sizes, int n_in,
                              void* d_out, int out_size) {
    const float* X  = (const float*)d_in[0];
    const int*   ei = (const int*)d_in[1];     // [2, E] int32
    const float* W1 = (const float*)d_in[2];
    const float* W2 = (const float*)d_in[3];
    float* out = (float*)d_out;

    int n_nodes = in_sizes[0] / D;             // 50000
    int n_edges = in_sizes[1] / 2;             // 640000

    static int n_sms = 0;
    if (n_sms == 0) {
        cudaDeviceGetAttribute(&n_sms, cudaDevAttrMultiProcessorCount, 0);
        if (n_sms <= 0) n_sms = 148;
        cudaFuncSetAttribute(fused_kernel,
                             cudaFuncAttributeMaxDynamicSharedMemorySize,
                             SMEM_TOTAL);
    }

    // One block per SM (200KB smem forces 1/SM; grid == SM count), so the
    // grid-wide per-chunk polling cannot deadlock.
    fused_kernel<<<n_sms, 1024, SMEM_TOTAL>>>(X, ei, W1, W2, out,
                                              n_nodes, n_edges);
}

// round 14
// speedup vs baseline: 1.5552x; 1.5552x over previous
#include <cuda_runtime.h>
#include <cuda_fp16.h>
#include <cuda_bf16.h>
#include <cstdint>

// Problem constants: N_NODES=50000, N_EDGES=640000, D=128, OUT=1
#define MAX_NODES 50000
#define D 128
#define TABLE_BYTES (MAX_NODES * 4)   // 200000 B of __half2
#define FILL_CHUNK 50000              // 4 chunks of 50000 B (16B multiple)
#define NPK_BLOCKS 152
#define NPK_THREADS 512               // 16 warps x 8 rows = 128 rows / iter
#define EDGE_BLOCKS 152
#define QUADS_PER_THREAD 2

// Packed per-node projections: lo = dot(X[n],W1), hi = dot(X[n],W2), fp16.
__device__ __align__(16) __half2 d_pack[MAX_NODES];

__device__ __forceinline__ float dot4(float4 a, float4 b) {
    return a.x * b.x + a.y * b.y + a.z * b.z + a.w * b.w;
}

// Kernel 1: grid-stride over 128-row tiles; 8 rows/warp, 8 lanes/row,
// fully-coalesced front-batched LDG.128 x8. Triggers PDL at entry so the
// edge kernel's CTAs launch + prefetch indices underneath this compute.
__global__ void __launch_bounds__(NPK_THREADS, 1)
node_proj_kernel(const float* __restrict__ X,
                 const float* __restrict__ W1,
                 const float* __restrict__ W2,
                 int n_nodes) {
    cudaTriggerProgrammaticLaunchCompletion();

    __shared__ __align__(16) float sW1[D];
    __shared__ __align__(16) float sW2[D];
    int tid = threadIdx.x;
    if (tid < D) {
        sW1[tid] = W1[tid];
        sW2[tid] = W2[tid];
    }
    __syncthreads();

    int lane = tid & 31;
    int sub  = lane & 7;
    int grp  = lane >> 3;
    int wid  = tid >> 5;            // 0..15

    const float4* Xv = reinterpret_cast<const float4*>(X);
    const float4* w1 = reinterpret_cast<const float4*>(sW1);
    const float4* w2 = reinterpret_cast<const float4*>(sW2);
    float4 w1_0 = w1[sub], w1_1 = w1[sub + 8], w1_2 = w1[sub + 16], w1_3 = w1[sub + 24];
    float4 w2_0 = w2[sub], w2_1 = w2[sub + 8], w2_2 = w2[sub + 16], w2_3 = w2[sub + 24];

    int n_tiles = (n_nodes + 127) / 128;        // 391
    for (int t = blockIdx.x; t < n_tiles; t += gridDim.x) {
        int n0 = t * 128 + wid * 8;             // this warp's 8-row group
        int rowA = n0 + grp;
        int rowB = n0 + 4 + grp;

        float sA1 = 0.f, sA2 = 0.f, sB1 = 0.f, sB2 = 0.f;
        if (rowA < n_nodes) {
            float4 a0 = Xv[(size_t)rowA * 32 + sub + 0];
            float4 a1 = Xv[(size_t)rowA * 32 + sub + 8];
            float4 a2 = Xv[(size_t)rowA * 32 + sub + 16];
            float4 a3 = Xv[(size_t)rowA * 32 + sub + 24];
            sA1 = dot4(a0, w1_0) + dot4(a1, w1_1) + dot4(a2, w1_2) + dot4(a3, w1_3);
            sA2 = dot4(a0, w2_0) + dot4(a1, w2_1) + dot4(a2, w2_2) + dot4(a3, w2_3);
        }
        if (rowB < n_nodes) {
            float4 b0 = Xv[(size_t)rowB * 32 + sub + 0];
            float4 b1 = Xv[(size_t)rowB * 32 + sub + 8];
            float4 b2 = Xv[(size_t)rowB * 32 + sub + 16];
            float4 b3 = Xv[(size_t)rowB * 32 + sub + 24];
            sB1 = dot4(b0, w1_0) + dot4(b1, w1_1) + dot4(b2, w1_2) + dot4(b3, w1_3);
            sB2 = dot4(b0, w2_0) + dot4(b1, w2_1) + dot4(b2, w2_2) + dot4(b3, w2_3);
        }

        #pragma unroll
        for (int off = 4; off > 0; off >>= 1) {
            sA1 += __shfl_xor_sync(0xFFFFFFFF, sA1, off);
            sA2 += __shfl_xor_sync(0xFFFFFFFF, sA2, off);
            sB1 += __shfl_xor_sync(0xFFFFFFFF, sB1, off);
            sB2 += __shfl_xor_sync(0xFFFFFFFF, sB2, off);
        }

        if (sub == 0) {
            if (rowA < n_nodes) d_pack[rowA] = __floats2half2_rn(sA1, sA2);
            if (rowB < n_nodes) d_pack[rowB] = __floats2half2_rn(sB1, sB2);
        }
    }
}

#define CLAMP(v) min(max((v), 0), MAX_NODES - 1)

// Kernel 2 (R9 architecture + PDL): launches under node_proj via PDL,
// inits mbarrier + prefetches edge indices early, then grid-dependency-syncs
// before bulk-filling the packed table and gathering from smem.
__global__ void __launch_bounds__(1024, 1)
edge_kernel_pack(const int* __restrict__ ei,
                 float* __restrict__ out,
                 int n_edges) {
    extern __shared__ __align__(16) unsigned char smem_raw[];
    __half2* s_p = reinterpret_cast<__half2*>(smem_raw);

    uint32_t smem_base;
    asm("{ .reg .u64 t; cvta.to.shared.u64 t, %1; cvt.u32.u64 %0, t; }"
        : "=r"(smem_base) : "l"(smem_raw));
    uint32_t mbar = smem_base + TABLE_BYTES;

    int tid = threadIdx.x;

    if (tid == 0) {
        asm volatile("mbarrier.init.shared.b64 [%0], 1;" :: "r"(mbar) : "memory");
    }
    __syncthreads();

    // ---- Prefetch ALL edge indices (ei is a harness input — safe before
    // the grid dependency sync; overlaps node_proj compute). ----
    int total_quads = n_edges >> 2;                   // 160000
    int qpb = (total_quads + gridDim.x - 1) / gridDim.x;
    int q_start = blockIdx.x * qpb;
    int q_end = min(q_start + qpb, total_quads);

    int  qs[QUADS_PER_THREAD];
    bool qv[QUADS_PER_THREAD];
    int4 sA[QUADS_PER_THREAD], dA[QUADS_PER_THREAD];
    #pragma unroll
    for (int k = 0; k < QUADS_PER_THREAD; k++) {
        int q = q_start + tid + k * 1024;
        qs[k] = q;
        qv[k] = q < q_end;
        if (qv[k]) {
            sA[k] = *reinterpret_cast<const int4*>(ei + q * 4);
            dA[k] = *reinterpret_cast<const int4*>(ei + n_edges + q * 4);
        }
    }

    // ---- Wait for node_proj completion, then issue the bulk fill ----
    if (tid == 0) {
        cudaGridDependencySynchronize();
        asm volatile("fence.proxy.async;" ::: "memory");

        asm volatile("mbarrier.arrive.expect_tx.shared.b64 _, [%0], %1;"
                     :: "r"(mbar), "r"((uint32_t)TABLE_BYTES) : "memory");
        const char* src = reinterpret_cast<const char*>(d_pack);
        #pragma unroll
        for (int c = 0; c < 4; c++) {
            asm volatile(
                "cp.async.bulk.shared::cta.global.mbarrier::complete_tx::bytes "
                "[%0], [%1], %2, [%3];"
                :: "r"(smem_base + c * FILL_CHUNK), "l"(src + (size_t)c * FILL_CHUNK),
                   "r"((uint32_t)FILL_CHUNK), "r"(mbar) : "memory");
        }
    }

    // ---- Wait for the table ----
    {
        uint32_t done;
        asm volatile(
            "{\n\t"
            ".reg .pred p;\n\t"
            "mbarrier.try_wait.parity.acquire.cta.shared::cta.b64 p, [%1], 0;\n\t"
            "selp.b32 %0, 1, 0, p;\n\t"
            "}"
            : "=r"(done) : "r"(mbar) : "memory");
        if (!done) {
            asm volatile(
                "{\n\t"
                ".reg .pred P1;\n\t"
                "WL_%=:\n\t"
                "mbarrier.try_wait.parity.acquire.cta.shared::cta.b64 P1, [%0], 0, 0x989680;\n\t"
                "@P1 bra.uni WD_%=;\n\t"
                "bra.uni WL_%=;\n\t"
                "WD_%=:\n\t"
                "}"
                :: "r"(mbar) : "memory");
        }
    }

    // ---- Gather + store ----
    #pragma unroll
    for (int k = 0; k < QUADS_PER_THREAD; k++) {
        if (qv[k]) {
            float4 r;
            r.x = __low2float(s_p[CLAMP(sA[k].x)]) + __high2float(s_p[CLAMP(dA[k].x)]);
            r.y = __low2float(s_p[CLAMP(sA[k].y)]) + __high2float(s_p[CLAMP(dA[k].y)]);
            r.z = __low2float(s_p[CLAMP(sA[k].z)]) + __high2float(s_p[CLAMP(dA[k].z)]);
            r.w = __low2float(s_p[CLAMP(sA[k].w)]) + __high2float(s_p[CLAMP(dA[k].w)]);
            *reinterpret_cast<float4*>(out + qs[k] * 4) = r;
        }
    }

    // Scalar tail (n_edges % 4 != 0) — block 0 only.
    if (blockIdx.x == 0) {
        for (int e = total_quads * 4 + tid; e < n_edges; e += blockDim.x) {
            int s = CLAMP(ei[e]);
            int d = CLAMP(ei[n_edges + e]);
            out[e] = __low2float(s_p[s]) + __high2float(s_p[d]);
        }
    }
}

extern "C" void kernel_launch(void* const* d_in, const int* in_sizes, int n_in,
                              void* d_out, int out_size) {
    const float* X  = (const float*)d_in[0];
    const int*   ei = (const int*)d_in[1];     // [2, E] int32
    const float* W1 = (const float*)d_in[2];
    const float* W2 = (const float*)d_in[3];
    float* out = (float*)d_out;

    int n_nodes = in_sizes[0] / D;             // 50000
    int n_edges = in_sizes[1] / 2;             // 640000

    static int inited = 0;
    if (!inited) {
        inited = 1;
        cudaFuncSetAttribute(edge_kernel_pack,
                             cudaFuncAttributeMaxDynamicSharedMemorySize,
                             TABLE_BYTES + 16);
    }

    // Kernel 1: 152 blocks x 512 threads, grid-stride over node tiles.
    node_proj_kernel<<<NPK_BLOCKS, NPK_THREADS>>>(X, W1, W2, n_nodes);

    // Kernel 2: PDL launch — CTAs come up under kernel 1, prefetch indices,
    // then grid-dependency-sync before reading d_pack.
    cudaLaunchConfig_t cfg = {};
    cfg.gridDim = dim3(EDGE_BLOCKS, 1, 1);
    cfg.blockDim = dim3(1024, 1, 1);
    cfg.dynamicSmemBytes = TABLE_BYTES + 16;
    cudaLaunchAttribute attrs[1];
    attrs[0].id = cudaLaunchAttributeProgrammaticStreamSerialization;
    attrs[0].val.programmaticStreamSerializationAllowed = 1;
    cfg.attrs = attrs;
    cfg.numAttrs = 1;
    cudaLaunchKernelEx(&cfg, edge_kernel_pack, ei, out, n_edges);
}

// round 15
// speedup vs baseline: 1.5970x; 1.0269x over previous
#include <cuda_runtime.h>
#include <cuda_fp16.h>
#include <cuda_bf16.h>
#include <cstdint>

// Problem constants: N_NODES=50000, N_EDGES=640000, D=128, OUT=1
#define MAX_NODES 50000
#define D 128
#define TABLE_BYTES (MAX_NODES * 4)   // 200000 B of __half2
#define EDGE_BLOCKS 152
#define QUADS_PER_THREAD 2

// Packed per-node projections: lo = dot(X[n],W1), hi = dot(X[n],W2), fp16.
__device__ __align__(16) __half2 d_pack[MAX_NODES];

__device__ __forceinline__ float dot4(float4 a, float4 b) {
    return a.x * b.x + a.y * b.y + a.z * b.z + a.w * b.w;
}

// Kernel 1 (R9-proven): 8 rows/warp, 8 lanes/row, fully-coalesced
// front-batched LDG.128 x8, 3-level group reduction.
__global__ void node_proj_kernel(const float* __restrict__ X,
                                 const float* __restrict__ W1,
                                 const float* __restrict__ W2,
                                 int n_nodes) {
    __shared__ __align__(16) float sW1[D];
    __shared__ __align__(16) float sW2[D];
    int tid = threadIdx.x;
    if (tid < D) {
        sW1[tid] = W1[tid];
        sW2[tid] = W2[tid];
    }
    __syncthreads();

    int lane = tid & 31;
    int sub  = lane & 7;
    int grp  = lane >> 3;
    int gwarp = (blockIdx.x * blockDim.x + tid) >> 5;
    int n0 = gwarp * 8;
    if (n0 >= n_nodes) return;

    int rowA = n0 + grp;
    int rowB = n0 + 4 + grp;

    const float4* Xv = reinterpret_cast<const float4*>(X);
    float4 a0 = Xv[(size_t)rowA * 32 + sub + 0];
    float4 a1 = Xv[(size_t)rowA * 32 + sub + 8];
    float4 a2 = Xv[(size_t)rowA * 32 + sub + 16];
    float4 a3 = Xv[(size_t)rowA * 32 + sub + 24];
    float4 b0 = Xv[(size_t)rowB * 32 + sub + 0];
    float4 b1 = Xv[(size_t)rowB * 32 + sub + 8];
    float4 b2 = Xv[(size_t)rowB * 32 + sub + 16];
    float4 b3 = Xv[(size_t)rowB * 32 + sub + 24];

    const float4* w1 = reinterpret_cast<const float4*>(sW1);
    const float4* w2 = reinterpret_cast<const float4*>(sW2);
    float4 w1_0 = w1[sub], w1_1 = w1[sub + 8], w1_2 = w1[sub + 16], w1_3 = w1[sub + 24];
    float4 w2_0 = w2[sub], w2_1 = w2[sub + 8], w2_2 = w2[sub + 16], w2_3 = w2[sub + 24];

    float sA1 = dot4(a0, w1_0) + dot4(a1, w1_1) + dot4(a2, w1_2) + dot4(a3, w1_3);
    float sA2 = dot4(a0, w2_0) + dot4(a1, w2_1) + dot4(a2, w2_2) + dot4(a3, w2_3);
    float sB1 = dot4(b0, w1_0) + dot4(b1, w1_1) + dot4(b2, w1_2) + dot4(b3, w1_3);
    float sB2 = dot4(b0, w2_0) + dot4(b1, w2_1) + dot4(b2, w2_2) + dot4(b3, w2_3);

    #pragma unroll
    for (int off = 4; off > 0; off >>= 1) {
        sA1 += __shfl_xor_sync(0xFFFFFFFF, sA1, off);
        sA2 += __shfl_xor_sync(0xFFFFFFFF, sA2, off);
        sB1 += __shfl_xor_sync(0xFFFFFFFF, sB1, off);
        sB2 += __shfl_xor_sync(0xFFFFFFFF, sB2, off);
    }

    if (sub == 0) {
        d_pack[rowA] = __floats2half2_rn(sA1, sA2);
        d_pack[rowB] = __floats2half2_rn(sB1, sB2);
    }
}

#define CLAMP(v) min(max((v), 0), MAX_NODES - 1)

// Kernel 2: table filled with cp.async (LDGSTS) from ALL 1024 threads —
// fire-and-forget 16B copies, no register round-trip, delivery on the
// L1<-L2 fill path instead of the (slower) per-SM bulk engine.
// Edge indices loaded before wait_group so they overlap the fill.
__global__ void __launch_bounds__(1024, 1)
edge_kernel_pack(const int* __restrict__ ei,
                 float* __restrict__ out,
                 int n_edges) {
    extern __shared__ __align__(16) unsigned char smem_raw[];
    __half2* s_p = reinterpret_cast<__half2*>(smem_raw);

    uint32_t smem_base;
    asm("{ .reg .u64 t; cvta.to.shared.u64 t, %1; cvt.u32.u64 %0, t; }"
        : "=r"(smem_base) : "l"(smem_raw));

    int tid = threadIdx.x;

    // ---- Issue the whole fill via cp.async.cg 16B ops (12500 total) ----
    {
        const char* src = reinterpret_cast<const char*>(d_pack);
        int n16 = TABLE_BYTES / 16;                // 12500
        for (int i = tid; i < n16; i += 1024) {
            uint32_t dst = smem_base + i * 16;
            asm volatile("cp.async.cg.shared.global [%0], [%1], 16;"
                         :: "r"(dst), "l"(src + (size_t)i * 16) : "memory");
        }
        asm volatile("cp.async.commit_group;" ::: "memory");
    }

    // ---- Load edge indices (overlaps the in-flight fill) ----
    int total_quads = n_edges >> 2;                   // 160000
    int qpb = (total_quads + gridDim.x - 1) / gridDim.x;
    int q_start = blockIdx.x * qpb;
    int q_end = min(q_start + qpb, total_quads);

    int  qs[QUADS_PER_THREAD];
    bool qv[QUADS_PER_THREAD];
    int4 sA[QUADS_PER_THREAD], dA[QUADS_PER_THREAD];
    #pragma unroll
    for (int k = 0; k < QUADS_PER_THREAD; k++) {
        int q = q_start + tid + k * 1024;
        qs[k] = q;
        qv[k] = q < q_end;
        if (qv[k]) {
            sA[k] = *reinterpret_cast<const int4*>(ei + q * 4);
            dA[k] = *reinterpret_cast<const int4*>(ei + n_edges + q * 4);
        }
    }

    // ---- Wait for own cp.async group, then block-wide barrier ----
    asm volatile("cp.async.wait_group 0;" ::: "memory");
    __syncthreads();

    // ---- Gather + store ----
    #pragma unroll
    for (int k = 0; k < QUADS_PER_THREAD; k++) {
        if (qv[k]) {
            float4 r;
            r.x = __low2float(s_p[CLAMP(sA[k].x)]) + __high2float(s_p[CLAMP(dA[k].x)]);
            r.y = __low2float(s_p[CLAMP(sA[k].y)]) + __high2float(s_p[CLAMP(dA[k].y)]);
            r.z = __low2float(s_p[CLAMP(sA[k].z)]) + __high2float(s_p[CLAMP(dA[k].z)]);
            r.w = __low2float(s_p[CLAMP(sA[k].w)]) + __high2float(s_p[CLAMP(dA[k].w)]);
            *reinterpret_cast<float4*>(out + qs[k] * 4) = r;
        }
    }

    // Scalar tail (n_edges % 4 != 0) — block 0 only.
    if (blockIdx.x == 0) {
        for (int e = total_quads * 4 + tid; e < n_edges; e += blockDim.x) {
            int s = CLAMP(ei[e]);
            int d = CLAMP(ei[n_edges + e]);
            out[e] = __low2float(s_p[s]) + __high2float(s_p[d]);
        }
    }
}

extern "C" void kernel_launch(void* const* d_in, const int* in_sizes, int n_in,
                              void* d_out, int out_size) {
    const float* X  = (const float*)d_in[0];
    const int*   ei = (const int*)d_in[1];     // [2, E] int32
    const float* W1 = (const float*)d_in[2];
    const float* W2 = (const float*)d_in[3];
    float* out = (float*)d_out;

    int n_nodes = in_sizes[0] / D;             // 50000
    int n_edges = in_sizes[1] / 2;             // 640000

    static int inited = 0;
    if (!inited) {
        inited = 1;
        cudaFuncSetAttribute(edge_kernel_pack,
                             cudaFuncAttributeMaxDynamicSharedMemorySize,
                             TABLE_BYTES);
    }

    // Kernel 1: 8 rows/warp, 256 threads/block = 64 rows/block
    int threads1 = 256;
    int blocks1 = (n_nodes + 63) / 64;
    node_proj_kernel<<<blocks1, threads1>>>(X, W1, W2, n_nodes);

    // Kernel 2: one block per SM; 200000 B table in dynamic smem.
    edge_kernel_pack<<<EDGE_BLOCKS, 1024, TABLE_BYTES>>>(ei, out, n_edges);
}